// round 8
// baseline (speedup 1.0000x reference)
#include <cuda_runtime.h>
#include <cstdint>
#include <cstddef>

// ============================================================================
// Problem constants
// ============================================================================
#define K_ALPHA 0.01f

static constexpr int MT = 4096;   // rows (2*2048)
static constexpr int NT = 11008;  // output features
static constexpr int KT = 4096;   // reduction

static constexpr int BM = 128;
static constexpr int BN = 128;
static constexpr int BK = 64;               // K bytes per pipeline chunk
static constexpr int KCHUNKS = KT / BK;     // 64
static constexpr int STAGES = 6;

static constexpr int A_STAGE = BM * BK;     // 8192
static constexpr int B_STAGE = BN * BK;     // 8192
static constexpr int STAGE_BYTES = A_STAGE + B_STAGE;      // 16384
static constexpr int SMEM_ALLOC = STAGES * STAGE_BYTES;    // 98304

// int8 scratch (device-global: allocation is forbidden)
__device__ __align__(16) signed char g_px[(size_t)MT * KT];  // 16.8 MB
__device__ __align__(16) signed char g_pw[(size_t)NT * KT];  // 45.1 MB

// ============================================================================
// PTX helpers — sm_103 BASE target only (no 'a'-suffix features!)
// ============================================================================
__device__ __forceinline__ unsigned smem_to_u32(const void* p) {
    unsigned a;
    asm("{ .reg .u64 t; cvta.to.shared.u64 t, %1; cvt.u32.u64 %0, t; }"
        : "=r"(a) : "l"(p));
    return a;
}

__device__ __forceinline__ void cp_async16(unsigned smem_addr, const void* gptr) {
    asm volatile("cp.async.cg.shared.global [%0], [%1], 16;"
                 :: "r"(smem_addr), "l"(gptr) : "memory");
}
__device__ __forceinline__ void cp_commit() {
    asm volatile("cp.async.commit_group;" ::: "memory");
}
template <int N>
__device__ __forceinline__ void cp_wait() {
    asm volatile("cp.async.wait_group %0;" :: "n"(N) : "memory");
}

__device__ __forceinline__ void ldsm_x4(unsigned (&r)[4], unsigned addr) {
    asm volatile("ldmatrix.sync.aligned.m8n8.x4.shared.b16 {%0,%1,%2,%3}, [%4];"
                 : "=r"(r[0]), "=r"(r[1]), "=r"(r[2]), "=r"(r[3]) : "r"(addr));
}

__device__ __forceinline__ void mma_s8(int (&c)[4], const unsigned (&a)[4],
                                       unsigned b0, unsigned b1) {
    asm volatile(
        "mma.sync.aligned.m16n8k32.row.col.s32.s8.s8.s32 "
        "{%0,%1,%2,%3}, {%4,%5,%6,%7}, {%8,%9}, {%0,%1,%2,%3};"
        : "+r"(c[0]), "+r"(c[1]), "+r"(c[2]), "+r"(c[3])
        : "r"(a[0]), "r"(a[1]), "r"(a[2]), "r"(a[3]), "r"(b0), "r"(b1));
}

// Swizzled smem address: rows of 64B, 4x16B chunks, chunk ^= (row>>1)&3.
// For ldmatrix (8 consecutive rows, fixed chunk) this yields 8 distinct
// 16B bank groups -> conflict-free LDSM.
__device__ __forceinline__ unsigned sw_addr(unsigned base, int r, int c) {
    return base + (unsigned)(r * 64) + (unsigned)(((c ^ ((r >> 1) & 3)) << 4));
}

// ============================================================================
// Pack: int32 containers -> dense int8 (16 values per thread)
// ============================================================================
__global__ void __launch_bounds__(256) pack_kernel(const int* __restrict__ src,
                                                   signed char* __restrict__ dst,
                                                   int n16) {
    int i = blockIdx.x * 256 + threadIdx.x;
    if (i >= n16) return;
    const int4* s = reinterpret_cast<const int4*>(src) + (size_t)i * 4;
    int4 a = s[0], b = s[1], c = s[2], d = s[3];
    int r0 = (a.x & 0xff) | ((a.y & 0xff) << 8) | ((a.z & 0xff) << 16) | ((a.w & 0xff) << 24);
    int r1 = (b.x & 0xff) | ((b.y & 0xff) << 8) | ((b.z & 0xff) << 16) | ((b.w & 0xff) << 24);
    int r2 = (c.x & 0xff) | ((c.y & 0xff) << 8) | ((c.z & 0xff) << 16) | ((c.w & 0xff) << 24);
    int r3 = (d.x & 0xff) | ((d.y & 0xff) << 8) | ((d.z & 0xff) << 16) | ((d.w & 0xff) << 24);
    reinterpret_cast<int4*>(dst)[i] = make_int4(r0, r1, r2, r3);
}

// ============================================================================
// GEMM: 128x128 tile / CTA, mma.sync m16n8k32 s8, 6-stage cp.async pipeline.
// 8 warps as 4(M) x 2(N); warp tile 32x64; per-thread accum 2x8x4 = 64 s32.
// ============================================================================
__global__ void __launch_bounds__(256, 2) gemm_kernel(const float* __restrict__ bias,
                                                      float* __restrict__ out) {
    extern __shared__ char smem[];
    unsigned smemU = smem_to_u32(smem);

    const int tid  = threadIdx.x;
    const int lane = tid & 31;
    const int wid  = tid >> 5;
    const int wm   = wid & 3;   // 0..3  (M direction, 32 rows each)
    const int wn   = wid >> 2;  // 0..1  (N direction, 64 cols each)
    const int m0   = blockIdx.y * BM;
    const int n0   = blockIdx.x * BN;

    // ---- per-thread load mapping: row = tid>>2 (+64 for pass 1), 16B chunk = tid&3
    const int lrow = tid >> 2;
    const int lcm  = tid & 3;
    const unsigned sA0 = sw_addr(0, lrow,      lcm);  // offsets within a stage
    const unsigned sA1 = sw_addr(0, lrow + 64, lcm);
    const signed char* gA0 = g_px + (size_t)(m0 + lrow) * KT + lcm * 16;
    const signed char* gA1 = gA0 + (size_t)64 * KT;
    const signed char* gB0 = g_pw + (size_t)(n0 + lrow) * KT + lcm * 16;
    const signed char* gB1 = gB0 + (size_t)64 * KT;

    auto load_stage = [&](int chunk, int slot) {
        unsigned aB = smemU + (unsigned)slot * STAGE_BYTES;
        unsigned bB = aB + A_STAGE;
        int ko = chunk * BK;
        cp_async16(aB + sA0, gA0 + ko);
        cp_async16(aB + sA1, gA1 + ko);
        cp_async16(bB + sA0, gB0 + ko);
        cp_async16(bB + sA1, gB1 + ko);
    };

    // ---- prologue: fill STAGES-1 slots
#pragma unroll
    for (int s = 0; s < STAGES - 1; ++s) { load_stage(s, s); cp_commit(); }

    int acc[2][8][4];
#pragma unroll
    for (int mi = 0; mi < 2; ++mi)
#pragma unroll
        for (int ni = 0; ni < 8; ++ni)
#pragma unroll
            for (int j = 0; j < 4; ++j) acc[mi][ni][j] = 0;

    // fragment row bases (per lane, invariant across chunks)
    const int frag_r = ((lane >> 3) & 1) * 8 + (lane & 7);  // row within 16-row group
    const int frag_c = lane >> 4;                            // 0/1: low/high 16B of k32

#pragma unroll 1
    for (int t = 0; t < KCHUNKS; ++t) {
        cp_wait<STAGES - 2>();
        __syncthreads();

        if (t + STAGES - 1 < KCHUNKS) load_stage(t + STAGES - 1, (t + STAGES - 1) % STAGES);
        cp_commit();

        unsigned aB = smemU + (unsigned)(t % STAGES) * STAGE_BYTES;
        unsigned bB = aB + A_STAGE;

#pragma unroll
        for (int ks = 0; ks < 2; ++ks) {
            const int cch = 2 * ks + frag_c;
            unsigned a[2][4];
#pragma unroll
            for (int mi = 0; mi < 2; ++mi) {
                int r = wm * 32 + mi * 16 + frag_r;
                ldsm_x4(a[mi], sw_addr(aB, r, cch));
            }
            unsigned b[8][2];
#pragma unroll
            for (int np = 0; np < 4; ++np) {
                int r = wn * 64 + np * 16 + frag_r;
                unsigned q[4];
                ldsm_x4(q, sw_addr(bB, r, cch));
                b[2 * np][0] = q[0]; b[2 * np + 1][0] = q[1];
                b[2 * np][1] = q[2]; b[2 * np + 1][1] = q[3];
            }
#pragma unroll
            for (int mi = 0; mi < 2; ++mi)
#pragma unroll
                for (int ni = 0; ni < 8; ++ni)
                    mma_s8(acc[mi][ni], a[mi], b[ni][0], b[ni][1]);
        }
    }

    // ---- epilogue: dequant + bias, float2 stores (each 32B-sector aligned)
    const int row0 = m0 + wm * 32 + (lane >> 2);
    const int colb = n0 + wn * 64 + (lane & 3) * 2;
#pragma unroll
    for (int ni = 0; ni < 8; ++ni) {
        const int c = colb + ni * 8;
        const float b0 = __ldg(bias + c);
        const float b1 = __ldg(bias + c + 1);
#pragma unroll
        for (int mi = 0; mi < 2; ++mi) {
            const int r = row0 + mi * 16;
            float2 v0, v1;
            v0.x = K_ALPHA * (float)acc[mi][ni][0] + b0;
            v0.y = K_ALPHA * (float)acc[mi][ni][1] + b1;
            v1.x = K_ALPHA * (float)acc[mi][ni][2] + b0;
            v1.y = K_ALPHA * (float)acc[mi][ni][3] + b1;
            *reinterpret_cast<float2*>(out + (size_t)r * NT + c)       = v0;
            *reinterpret_cast<float2*>(out + (size_t)(r + 8) * NT + c) = v1;
        }
    }
}

// ============================================================================
// Launch
// ============================================================================
extern "C" void kernel_launch(void* const* d_in, const int* in_sizes, int n_in,
                              void* d_out, int out_size) {
    const int*   x    = (const int*)d_in[0];     // [2,2048,4096] int8-in-int32
    const int*   w    = (const int*)d_in[1];     // [11008,4096]  int8-in-int32
    const float* bias = (const float*)d_in[2];   // [1,11008]
    float*       out  = (float*)d_out;           // [4096,11008]

    void* px = nullptr;
    void* pw = nullptr;
    cudaGetSymbolAddress(&px, g_px);
    cudaGetSymbolAddress(&pw, g_pw);

    int nx16 = (MT * KT) / 16;   // 1,048,576
    int nw16 = (NT * KT) / 16;   // 2,818,048
    pack_kernel<<<(nx16 + 255) / 256, 256>>>(x, (signed char*)px, nx16);
    pack_kernel<<<(nw16 + 255) / 256, 256>>>(w, (signed char*)pw, nw16);

    cudaFuncSetAttribute(gemm_kernel, cudaFuncAttributeMaxDynamicSharedMemorySize,
                         SMEM_ALLOC);
    gemm_kernel<<<dim3(NT / BN, MT / BM), 256, SMEM_ALLOC>>>(bias, out);
}